// round 1
// baseline (speedup 1.0000x reference)
#include <cuda_runtime.h>
#include <math.h>

// Problem dims (fixed by the reference)
#define BB    4
#define TSEQ  2048
#define CDIM  1024
#define HEADS 16
#define DHEAD 64
#define MTOT  (BB * TSEQ)     // 8192
#define FDIM  (4 * CDIM)      // 4096

// -------------------- scratch (device globals; no allocs allowed) ---------
__device__ float g_h   [MTOT * CDIM];   // LN1 out, reused for LN2 out
__device__ float g_q   [MTOT * CDIM];
__device__ float g_k   [MTOT * CDIM];
__device__ float g_v   [MTOT * CDIM];
__device__ float g_attn[MTOT * CDIM];
__device__ float g_x1  [MTOT * CDIM];   // x + attn proj (residual 1)
__device__ float g_ff  [MTOT * FDIM];   // FFN hidden

// -------------------- LayerNorm ------------------------------------------
__inline__ __device__ float warp_sum(float v) {
    #pragma unroll
    for (int m = 16; m > 0; m >>= 1) v += __shfl_xor_sync(0xffffffffu, v, m);
    return v;
}

__global__ void __launch_bounds__(256) layernorm_kernel(
    const float* __restrict__ x, const float* __restrict__ g,
    const float* __restrict__ bt, float* __restrict__ y)
{
    const int row = blockIdx.x;
    const int tid = threadIdx.x;                 // 256 threads, 4 floats each
    const float4 v = ((const float4*)(x + (size_t)row * CDIM))[tid];

    float s  = v.x + v.y + v.z + v.w;
    float ss = v.x*v.x + v.y*v.y + v.z*v.z + v.w*v.w;

    __shared__ float sh1[8], sh2[8];
    s = warp_sum(s); ss = warp_sum(ss);
    const int w = tid >> 5, l = tid & 31;
    if (l == 0) { sh1[w] = s; sh2[w] = ss; }
    __syncthreads();
    if (w == 0) {
        float a = (l < 8) ? sh1[l] : 0.f;
        float b = (l < 8) ? sh2[l] : 0.f;
        a = warp_sum(a); b = warp_sum(b);
        if (l == 0) { sh1[0] = a; sh2[0] = b; }
    }
    __syncthreads();

    const float mean = sh1[0] * (1.0f / CDIM);
    const float var  = sh2[0] * (1.0f / CDIM) - mean * mean;
    const float inv  = rsqrtf(var + 1e-5f);

    const float4 gv = ((const float4*)g)[tid];
    const float4 bv = ((const float4*)bt)[tid];
    float4 o;
    o.x = (v.x - mean) * inv * gv.x + bv.x;
    o.y = (v.y - mean) * inv * gv.y + bv.y;
    o.z = (v.z - mean) * inv * gv.z + bv.z;
    o.w = (v.w - mean) * inv * gv.w + bv.w;
    ((float4*)(y + (size_t)row * CDIM))[tid] = o;
}

// -------------------- SGEMM: C = A[MxK] @ B[KxN] (+bias, relu, +res) ------
// 128x128 tile, BK=8, 256 threads, 8x8 per-thread microtile.
template<bool BIAS, bool RELU, bool RES>
__global__ void __launch_bounds__(256) sgemm_kernel(
    const float* __restrict__ A, const float* __restrict__ B,
    const float* __restrict__ bias, const float* __restrict__ res,
    float* __restrict__ C, int M, int N, int K)
{
    __shared__ float As[8][128];   // transposed A tile
    __shared__ float Bs[8][128];

    const int tid = threadIdx.x;
    const int m0 = blockIdx.y * 128;
    const int n0 = blockIdx.x * 128;

    const int arow = tid >> 1;            // 0..127
    const int acol = (tid & 1) << 2;      // 0 or 4
    const int brow = tid >> 5;            // 0..7
    const int bcol = (tid & 31) << 2;     // 0..124

    const int ty = tid >> 4;              // 0..15 -> rows ty*8..
    const int tx = tid & 15;              // 0..15 -> cols tx*8..

    const float* Aptr = A + (size_t)(m0 + arow) * K + acol;
    const float* Bptr = B + (size_t)brow * N + (n0 + bcol);

    float acc[8][8];
    #pragma unroll
    for (int i = 0; i < 8; i++)
        #pragma unroll
        for (int j = 0; j < 8; j++) acc[i][j] = 0.f;

    for (int k0 = 0; k0 < K; k0 += 8) {
        const float4 av = *(const float4*)(Aptr + k0);
        const float4 bv = *(const float4*)(Bptr + (size_t)k0 * N);
        As[acol + 0][arow] = av.x;
        As[acol + 1][arow] = av.y;
        As[acol + 2][arow] = av.z;
        As[acol + 3][arow] = av.w;
        *(float4*)&Bs[brow][bcol] = bv;
        __syncthreads();

        #pragma unroll
        for (int kk = 0; kk < 8; kk++) {
            float a[8], b[8];
            *(float4*)&a[0] = *(const float4*)&As[kk][ty * 8];
            *(float4*)&a[4] = *(const float4*)&As[kk][ty * 8 + 4];
            *(float4*)&b[0] = *(const float4*)&Bs[kk][tx * 8];
            *(float4*)&b[4] = *(const float4*)&Bs[kk][tx * 8 + 4];
            #pragma unroll
            for (int i = 0; i < 8; i++)
                #pragma unroll
                for (int j = 0; j < 8; j++)
                    acc[i][j] = fmaf(a[i], b[j], acc[i][j]);
        }
        __syncthreads();
    }

    #pragma unroll
    for (int i = 0; i < 8; i++) {
        const int row = m0 + ty * 8 + i;
        #pragma unroll
        for (int j4 = 0; j4 < 8; j4 += 4) {
            const int col = n0 + tx * 8 + j4;
            float4 c;
            c.x = acc[i][j4 + 0]; c.y = acc[i][j4 + 1];
            c.z = acc[i][j4 + 2]; c.w = acc[i][j4 + 3];
            if (BIAS) {
                const float4 bb = *(const float4*)&bias[col];
                c.x += bb.x; c.y += bb.y; c.z += bb.z; c.w += bb.w;
            }
            if (RELU) {
                c.x = fmaxf(c.x, 0.f); c.y = fmaxf(c.y, 0.f);
                c.z = fmaxf(c.z, 0.f); c.w = fmaxf(c.w, 0.f);
            }
            if (RES) {
                const float4 rr = *(const float4*)&res[(size_t)row * N + col];
                c.x += rr.x; c.y += rr.y; c.z += rr.z; c.w += rr.w;
            }
            *(float4*)&C[(size_t)row * N + col] = c;
        }
    }
}

// -------------------- Flash attention (causal, fp32) ----------------------
// grid (T/64, H, B), 256 threads. 64x64 Q/K/V tiles, D=64.
// KPs holds K^T during S compute, then is overwritten with P for the PV GEMM.
__global__ void __launch_bounds__(256) flash_attn_kernel(
    const float* __restrict__ Q, const float* __restrict__ K,
    const float* __restrict__ V, float* __restrict__ O)
{
    __shared__ float Qs [64][64];
    __shared__ float KPs[64][64];
    __shared__ float Vs [64][64];

    const int tid = threadIdx.x;
    const int qt = blockIdx.x, hh = blockIdx.y, bb = blockIdx.z;
    const int ty = tid >> 4, tx = tid & 15;   // 16x16 thread grid, 4x4 each

    const size_t baseQ = ((size_t)(bb * TSEQ + qt * 64)) * CDIM + hh * DHEAD;

    // load Q tile (coalesced), fold in 1/sqrt(D) = 0.125
    #pragma unroll
    for (int it = 0; it < 4; it++) {
        const int idx = it * 256 + tid;       // float4 index 0..1023
        const int r = idx >> 4;
        const int c = (idx & 15) << 2;
        float4 t = *(const float4*)&Q[baseQ + (size_t)r * CDIM + c];
        t.x *= 0.125f; t.y *= 0.125f; t.z *= 0.125f; t.w *= 0.125f;
        *(float4*)&Qs[r][c] = t;
    }

    float m[4], lsum[4], o[4][4];
    #pragma unroll
    for (int i = 0; i < 4; i++) {
        m[i] = -1e30f; lsum[i] = 0.f;
        #pragma unroll
        for (int j = 0; j < 4; j++) o[i][j] = 0.f;
    }

    for (int kt = 0; kt <= qt; kt++) {
        __syncthreads();  // previous PV reads of KPs/Vs complete
        const size_t baseK = ((size_t)(bb * TSEQ + kt * 64)) * CDIM + hh * DHEAD;
        #pragma unroll
        for (int it = 0; it < 4; it++) {
            const int idx = it * 256 + tid;
            const int r = idx >> 4;
            const int c = (idx & 15) << 2;
            const float4 tk = *(const float4*)&K[baseK + (size_t)r * CDIM + c];
            KPs[c + 0][r] = tk.x;   // transposed store
            KPs[c + 1][r] = tk.y;
            KPs[c + 2][r] = tk.z;
            KPs[c + 3][r] = tk.w;
            const float4 tv = *(const float4*)&V[baseK + (size_t)r * CDIM + c];
            *(float4*)&Vs[r][c] = tv;
        }
        __syncthreads();

        // S = (Q*scale) @ K^T  — 4x4 per thread
        float s[4][4];
        #pragma unroll
        for (int i = 0; i < 4; i++)
            #pragma unroll
            for (int j = 0; j < 4; j++) s[i][j] = 0.f;

        #pragma unroll 16
        for (int d = 0; d < 64; d++) {
            float a[4], b[4];
            #pragma unroll
            for (int i = 0; i < 4; i++) a[i] = Qs[ty * 4 + i][d];
            #pragma unroll
            for (int j = 0; j < 4; j++) b[j] = KPs[d][tx * 4 + j];
            #pragma unroll
            for (int i = 0; i < 4; i++)
                #pragma unroll
                for (int j = 0; j < 4; j++)
                    s[i][j] = fmaf(a[i], b[j], s[i][j]);
        }

        if (kt == qt) {   // causal mask on the diagonal tile
            #pragma unroll
            for (int i = 0; i < 4; i++)
                #pragma unroll
                for (int j = 0; j < 4; j++)
                    if (tx * 4 + j > ty * 4 + i) s[i][j] = -1e30f;
        }

        // online softmax (rows owned by the 16 tx-lanes of each ty)
        float p[4][4];
        #pragma unroll
        for (int i = 0; i < 4; i++) {
            float mx = fmaxf(fmaxf(s[i][0], s[i][1]), fmaxf(s[i][2], s[i][3]));
            #pragma unroll
            for (int off = 1; off < 16; off <<= 1)
                mx = fmaxf(mx, __shfl_xor_sync(0xffffffffu, mx, off));
            const float mn = fmaxf(m[i], mx);
            const float alpha = __expf(m[i] - mn);
            m[i] = mn;
            float rs = 0.f;
            #pragma unroll
            for (int j = 0; j < 4; j++) {
                p[i][j] = __expf(s[i][j] - mn);
                rs += p[i][j];
            }
            #pragma unroll
            for (int off = 1; off < 16; off <<= 1)
                rs += __shfl_xor_sync(0xffffffffu, rs, off);
            lsum[i] = lsum[i] * alpha + rs;
            #pragma unroll
            for (int j = 0; j < 4; j++) o[i][j] *= alpha;
        }

        __syncthreads();  // all S reads of KPs done; safe to overwrite with P
        #pragma unroll
        for (int i = 0; i < 4; i++)
            #pragma unroll
            for (int j = 0; j < 4; j++)
                KPs[ty * 4 + i][tx * 4 + j] = p[i][j];
        __syncthreads();

        // O += P @ V
        #pragma unroll 16
        for (int kk = 0; kk < 64; kk++) {
            float a[4], b[4];
            #pragma unroll
            for (int i = 0; i < 4; i++) a[i] = KPs[ty * 4 + i][kk];
            #pragma unroll
            for (int j = 0; j < 4; j++) b[j] = Vs[kk][tx * 4 + j];
            #pragma unroll
            for (int i = 0; i < 4; i++)
                #pragma unroll
                for (int j = 0; j < 4; j++)
                    o[i][j] = fmaf(a[i], b[j], o[i][j]);
        }
    }

    #pragma unroll
    for (int i = 0; i < 4; i++) {
        const float invl = 1.0f / lsum[i];
        float4 t;
        t.x = o[i][0] * invl; t.y = o[i][1] * invl;
        t.z = o[i][2] * invl; t.w = o[i][3] * invl;
        *(float4*)&O[baseQ + (size_t)(ty * 4 + i) * CDIM + tx * 4] = t;
    }
}

// -------------------- launch ----------------------------------------------
extern "C" void kernel_launch(void* const* d_in, const int* in_sizes, int n_in,
                              void* d_out, int out_size)
{
    (void)in_sizes; (void)n_in; (void)out_size;
    const float* x    = (const float*)d_in[0];
    const float* Wq   = (const float*)d_in[1];
    const float* Wk   = (const float*)d_in[2];
    const float* Wv   = (const float*)d_in[3];
    const float* Wo   = (const float*)d_in[4];
    const float* bo   = (const float*)d_in[5];
    const float* ln1g = (const float*)d_in[6];
    const float* ln1b = (const float*)d_in[7];
    const float* ln2g = (const float*)d_in[8];
    const float* ln2b = (const float*)d_in[9];
    const float* W1   = (const float*)d_in[10];
    const float* b1   = (const float*)d_in[11];
    const float* W2   = (const float*)d_in[12];
    const float* b2   = (const float*)d_in[13];
    float* out = (float*)d_out;

    float *h, *q, *k, *v, *attn, *x1, *ff;
    cudaGetSymbolAddress((void**)&h,    g_h);
    cudaGetSymbolAddress((void**)&q,    g_q);
    cudaGetSymbolAddress((void**)&k,    g_k);
    cudaGetSymbolAddress((void**)&v,    g_v);
    cudaGetSymbolAddress((void**)&attn, g_attn);
    cudaGetSymbolAddress((void**)&x1,   g_x1);
    cudaGetSymbolAddress((void**)&ff,   g_ff);

    const dim3 blk(256);
    const dim3 gc(CDIM / 128, MTOT / 128);   // (8, 64)
    const dim3 gf(FDIM / 128, MTOT / 128);   // (32, 64)

    // 1) h = LN1(x)
    layernorm_kernel<<<MTOT, blk>>>(x, ln1g, ln1b, h);
    // 2) q,k,v = h @ W{q,k,v}
    sgemm_kernel<false, false, false><<<gc, blk>>>(h, Wq, nullptr, nullptr, q, MTOT, CDIM, CDIM);
    sgemm_kernel<false, false, false><<<gc, blk>>>(h, Wk, nullptr, nullptr, k, MTOT, CDIM, CDIM);
    sgemm_kernel<false, false, false><<<gc, blk>>>(h, Wv, nullptr, nullptr, v, MTOT, CDIM, CDIM);
    // 3) causal attention
    flash_attn_kernel<<<dim3(TSEQ / 64, HEADS, BB), blk>>>(q, k, v, attn);
    // 4) x1 = x + attn @ Wo + bo
    sgemm_kernel<true, false, true><<<gc, blk>>>(attn, Wo, bo, x, x1, MTOT, CDIM, CDIM);
    // 5) h = LN2(x1)
    layernorm_kernel<<<MTOT, blk>>>(x1, ln2g, ln2b, h);
    // 6) ff = relu(h @ W1 + b1)
    sgemm_kernel<true, true, false><<<gf, blk>>>(h, W1, b1, nullptr, ff, MTOT, FDIM, CDIM);
    // 7) out = x1 + ff @ W2 + b2
    sgemm_kernel<true, false, true><<<gc, blk>>>(ff, W2, b2, x1, out, MTOT, CDIM, FDIM);
}

// round 3
// speedup vs baseline: 1.8012x; 1.8012x over previous
#include <cuda_runtime.h>
#include <cuda_bf16.h>
#include <cstdint>
#include <math.h>

// Problem dims (fixed by the reference)
#define BB    4
#define TSEQ  2048
#define CDIM  1024
#define HEADS 16
#define DHEAD 64
#define MTOT  (BB * TSEQ)     // 8192
#define FDIM  (4 * CDIM)      // 4096

typedef __nv_bfloat16 bf16;
typedef __nv_bfloat162 bf162;

// -------------------- scratch (device globals; no allocs allowed) ---------
__device__ bf16  g_hhi [MTOT * CDIM];   // LN out hi (reused LN1/LN2)
__device__ bf16  g_hlo [MTOT * CDIM];
__device__ float g_q   [MTOT * CDIM];
__device__ float g_k   [MTOT * CDIM];
__device__ float g_v   [MTOT * CDIM];
__device__ bf16  g_ahi [MTOT * CDIM];   // attention out hi/lo
__device__ bf16  g_alo [MTOT * CDIM];
__device__ float g_x1  [MTOT * CDIM];
__device__ bf16  g_ffhi[MTOT * FDIM];
__device__ bf16  g_fflo[MTOT * FDIM];
// split weights (row-major [K][N], same layout as inputs)
__device__ bf16 g_Wqhi[CDIM * CDIM], g_Wqlo[CDIM * CDIM];
__device__ bf16 g_Wkhi[CDIM * CDIM], g_Wklo[CDIM * CDIM];
__device__ bf16 g_Wvhi[CDIM * CDIM], g_Wvlo[CDIM * CDIM];
__device__ bf16 g_Wohi[CDIM * CDIM], g_Wolo[CDIM * CDIM];
__device__ bf16 g_W1hi[CDIM * FDIM], g_W1lo[CDIM * FDIM];
__device__ bf16 g_W2hi[FDIM * CDIM], g_W2lo[FDIM * CDIM];

// ==================== PTX helpers (all plain sm_80+ features) =============
__device__ __forceinline__ uint32_t smem_u32(const void* p) {
    uint32_t a;
    asm("{ .reg .u64 t; cvta.to.shared.u64 t, %1; cvt.u32.u64 %0, t; }"
        : "=r"(a) : "l"(p));
    return a;
}
__device__ __forceinline__ void cp16(uint32_t dst, const void* src) {
    asm volatile("cp.async.cg.shared.global [%0], [%1], 16;"
                 :: "r"(dst), "l"(src));
}
__device__ __forceinline__ void cp_commit() {
    asm volatile("cp.async.commit_group;");
}
template<int N> __device__ __forceinline__ void cp_wait() {
    asm volatile("cp.async.wait_group %0;" :: "n"(N));
}
__device__ __forceinline__ void ldsm_x4(uint32_t* r, uint32_t addr) {
    asm volatile("ldmatrix.sync.aligned.m8n8.x4.shared.b16 {%0,%1,%2,%3}, [%4];"
                 : "=r"(r[0]), "=r"(r[1]), "=r"(r[2]), "=r"(r[3]) : "r"(addr));
}
__device__ __forceinline__ void ldsm_x2t(uint32_t* r, uint32_t addr) {
    asm volatile("ldmatrix.sync.aligned.m8n8.x2.trans.shared.b16 {%0,%1}, [%2];"
                 : "=r"(r[0]), "=r"(r[1]) : "r"(addr));
}
__device__ __forceinline__ void mma_bf16(float* c, const uint32_t* a, const uint32_t* b) {
    asm volatile(
        "mma.sync.aligned.m16n8k16.row.col.f32.bf16.bf16.f32 "
        "{%0,%1,%2,%3}, {%4,%5,%6,%7}, {%8,%9}, {%0,%1,%2,%3};"
        : "+f"(c[0]), "+f"(c[1]), "+f"(c[2]), "+f"(c[3])
        : "r"(a[0]), "r"(a[1]), "r"(a[2]), "r"(a[3]), "r"(b[0]), "r"(b[1]));
}
__device__ __forceinline__ void split1(float v, bf16& h, bf16& l) {
    h = __float2bfloat16_rn(v);
    l = __float2bfloat16_rn(v - __bfloat162float(h));
}

// ==================== bf16x3 mma.sync GEMM =================================
// C[M,N] = A[M,K] @ B[K,N]; A,B pre-split into hi/lo bf16 (row-major).
// 128x128 CTA tile, BK=32, 256 threads (2x4 warps, 64x32 warp tile),
// double-buffered cp.async.
#define GT 256
#define A_TILE 10240   // 128 rows x 80B (32 bf16 + 8 pad)
#define B_TILE 8704    // 32 rows x 272B (128 bf16 + 8 pad)
#define OFF_AL 20480
#define OFF_BH 40960
#define OFF_BL 58368
#define GEMM_SMEM 75776

template<bool BIAS, bool RELU, bool RES, bool SPLIT>
__global__ void __launch_bounds__(GT) mma_gemm_kernel(
    const bf16* __restrict__ Ahi, const bf16* __restrict__ Alo,
    const bf16* __restrict__ Bhi, const bf16* __restrict__ Blo,
    const float* __restrict__ bias, const float* __restrict__ res,
    float* __restrict__ Cf, bf16* __restrict__ Chi, bf16* __restrict__ Clo,
    int N, int K)
{
    extern __shared__ char sm[];
    const uint32_t sb = smem_u32(sm);

    const int tid  = threadIdx.x;
    const int lane = tid & 31;
    const int wid  = tid >> 5;
    const int wm = (wid >> 2) * 64;     // warp M offset in tile
    const int wn = (wid & 3) * 32;      // warp N offset in tile
    const int m0 = blockIdx.y * 128;
    const int n0 = blockIdx.x * 128;

    // cp.async mapping
    const int ar0 = tid >> 1;                 // A: 2 chunks/thread: rows tid/2, segs
    const int as0 = (tid & 1) << 1;           // seg 0/2 then +1
    const int br0 = tid >> 4;                 // B: rows tid/16
    const int bs0 = tid & 15;                 // seg

    auto load_stage = [&](int s, int c) {
        const int kc = c << 5;
        const uint32_t aoff = sb + s * A_TILE;
        const uint32_t boff = sb + OFF_BH + s * B_TILE;
        // A: 128 rows x 64B (4 segs); each thread: row=tid/2, segs {as0, as0+1}
        {
            const size_t g = (size_t)(m0 + ar0) * K + kc + as0 * 8;
            const uint32_t so = aoff + ar0 * 80 + as0 * 16;
            cp16(so,       Ahi + g);
            cp16(so + 16,  Ahi + g + 8);
            cp16(so + OFF_AL,      Alo + g);
            cp16(so + OFF_AL + 16, Alo + g + 8);
        }
        // B: 32 rows x 256B (16 segs); each thread: row=tid/16, seg=tid%16, x2 rows
        {
            const size_t g = (size_t)(kc + br0) * N + n0 + bs0 * 8;
            const uint32_t so = boff + br0 * 272 + bs0 * 16;
            cp16(so, Bhi + g);
            cp16(so + (OFF_BL - OFF_BH), Blo + g);
            const size_t g2 = g + (size_t)16 * N;
            const uint32_t so2 = so + 16 * 272;
            cp16(so2, Bhi + g2);
            cp16(so2 + (OFF_BL - OFF_BH), Blo + g2);
        }
    };

    float acc[4][4][4];
    #pragma unroll
    for (int a = 0; a < 4; a++)
        #pragma unroll
        for (int b = 0; b < 4; b++)
            #pragma unroll
            for (int d = 0; d < 4; d++) acc[a][b][d] = 0.f;

    const int NC = K >> 5;
    load_stage(0, 0);
    cp_commit();

    for (int c = 0; c < NC; c++) {
        const int s = c & 1;
        if (c + 1 < NC) {
            load_stage(s ^ 1, c + 1);
            cp_commit();
            cp_wait<1>();
        } else {
            cp_wait<0>();
        }
        __syncthreads();

        const uint32_t aH = sb + s * A_TILE;
        const uint32_t bH = sb + OFF_BH + s * B_TILE;
        #pragma unroll
        for (int ks = 0; ks < 2; ks++) {
            uint32_t bh[4][2], bl[4][2];
            #pragma unroll
            for (int nt = 0; nt < 4; nt++) {
                const uint32_t ba = bH + (ks * 16 + (lane & 15)) * 272
                                       + (wn + nt * 8) * 2;
                ldsm_x2t(bh[nt], ba);
                ldsm_x2t(bl[nt], ba + (OFF_BL - OFF_BH));
            }
            #pragma unroll
            for (int mt = 0; mt < 4; mt++) {
                uint32_t ah[4], al[4];
                const uint32_t aa = aH + (wm + mt * 16 + (lane & 15)) * 80
                                       + (ks * 16 + (lane >> 4) * 8) * 2;
                ldsm_x4(ah, aa);
                ldsm_x4(al, aa + OFF_AL);
                #pragma unroll
                for (int nt = 0; nt < 4; nt++) {
                    mma_bf16(acc[mt][nt], ah, bh[nt]);
                    mma_bf16(acc[mt][nt], ah, bl[nt]);
                    mma_bf16(acc[mt][nt], al, bh[nt]);
                }
            }
        }
        __syncthreads();
    }

    // ---- epilogue ----
    #pragma unroll
    for (int mt = 0; mt < 4; mt++) {
        #pragma unroll
        for (int nt = 0; nt < 4; nt++) {
            #pragma unroll
            for (int half = 0; half < 2; half++) {
                const int row = m0 + wm + mt * 16 + (lane >> 2) + half * 8;
                const int col = n0 + wn + nt * 8 + (lane & 3) * 2;
                float v0 = acc[mt][nt][half * 2 + 0];
                float v1 = acc[mt][nt][half * 2 + 1];
                if (BIAS) { v0 += bias[col]; v1 += bias[col + 1]; }
                if (RELU) { v0 = fmaxf(v0, 0.f); v1 = fmaxf(v1, 0.f); }
                if (RES) {
                    const float2 rr = *(const float2*)&res[(size_t)row * N + col];
                    v0 += rr.x; v1 += rr.y;
                }
                if (SPLIT) {
                    bf16 h0, l0, h1, l1;
                    split1(v0, h0, l0);
                    split1(v1, h1, l1);
                    const bf162 ph = __halves2bfloat162(h0, h1);
                    const bf162 pl = __halves2bfloat162(l0, l1);
                    *(uint32_t*)&Chi[(size_t)row * N + col] = *(const uint32_t*)&ph;
                    *(uint32_t*)&Clo[(size_t)row * N + col] = *(const uint32_t*)&pl;
                } else {
                    float2 o; o.x = v0; o.y = v1;
                    *(float2*)&Cf[(size_t)row * N + col] = o;
                }
            }
        }
    }
}

// ==================== weight split (fp32 -> bf16 hi/lo) ====================
__global__ void __launch_bounds__(256) wsplit_kernel(
    const float* __restrict__ w, bf16* __restrict__ hi, bf16* __restrict__ lo,
    int n4)
{
    for (int i = blockIdx.x * blockDim.x + threadIdx.x; i < n4;
         i += gridDim.x * blockDim.x) {
        const float4 v = ((const float4*)w)[i];
        bf16 h0, h1, h2, h3, l0, l1, l2, l3;
        split1(v.x, h0, l0); split1(v.y, h1, l1);
        split1(v.z, h2, l2); split1(v.w, h3, l3);
        const bf162 ha = __halves2bfloat162(h0, h1);
        const bf162 hb = __halves2bfloat162(h2, h3);
        const bf162 la = __halves2bfloat162(l0, l1);
        const bf162 lb = __halves2bfloat162(l2, l3);
        uint2 uh, ul;
        uh.x = *(const uint32_t*)&ha; uh.y = *(const uint32_t*)&hb;
        ul.x = *(const uint32_t*)&la; ul.y = *(const uint32_t*)&lb;
        *(uint2*)&hi[(size_t)i * 4] = uh;
        *(uint2*)&lo[(size_t)i * 4] = ul;
    }
}

// ==================== LayerNorm (fp32 in -> bf16 hi/lo out) ================
__inline__ __device__ float warp_sum(float v) {
    #pragma unroll
    for (int m = 16; m > 0; m >>= 1) v += __shfl_xor_sync(0xffffffffu, v, m);
    return v;
}

__global__ void __launch_bounds__(256) layernorm_split_kernel(
    const float* __restrict__ x, const float* __restrict__ g,
    const float* __restrict__ bt, bf16* __restrict__ yhi, bf16* __restrict__ ylo)
{
    const int row = blockIdx.x;
    const int tid = threadIdx.x;
    const float4 v = ((const float4*)(x + (size_t)row * CDIM))[tid];

    float s  = v.x + v.y + v.z + v.w;
    float ss = v.x*v.x + v.y*v.y + v.z*v.z + v.w*v.w;

    __shared__ float sh1[8], sh2[8];
    s = warp_sum(s); ss = warp_sum(ss);
    const int w = tid >> 5, l = tid & 31;
    if (l == 0) { sh1[w] = s; sh2[w] = ss; }
    __syncthreads();
    if (w == 0) {
        float a = (l < 8) ? sh1[l] : 0.f;
        float b = (l < 8) ? sh2[l] : 0.f;
        a = warp_sum(a); b = warp_sum(b);
        if (l == 0) { sh1[0] = a; sh2[0] = b; }
    }
    __syncthreads();

    const float mean = sh1[0] * (1.0f / CDIM);
    const float var  = sh2[0] * (1.0f / CDIM) - mean * mean;
    const float inv  = rsqrtf(var + 1e-5f);

    const float4 gv = ((const float4*)g)[tid];
    const float4 bv = ((const float4*)bt)[tid];
    float o0 = (v.x - mean) * inv * gv.x + bv.x;
    float o1 = (v.y - mean) * inv * gv.y + bv.y;
    float o2 = (v.z - mean) * inv * gv.z + bv.z;
    float o3 = (v.w - mean) * inv * gv.w + bv.w;

    bf16 h0, h1, h2, h3, l0, l1, l2, l3;
    split1(o0, h0, l0); split1(o1, h1, l1);
    split1(o2, h2, l2); split1(o3, h3, l3);
    const bf162 ha = __halves2bfloat162(h0, h1);
    const bf162 hb = __halves2bfloat162(h2, h3);
    const bf162 la = __halves2bfloat162(l0, l1);
    const bf162 lb = __halves2bfloat162(l2, l3);
    uint2 uh, ul;
    uh.x = *(const uint32_t*)&ha; uh.y = *(const uint32_t*)&hb;
    ul.x = *(const uint32_t*)&la; ul.y = *(const uint32_t*)&lb;
    *(uint2*)&yhi[(size_t)row * CDIM + tid * 4] = uh;
    *(uint2*)&ylo[(size_t)row * CDIM + tid * 4] = ul;
}

// ==================== Flash attention (causal, fp32, split output) =========
__global__ void __launch_bounds__(256) flash_attn_kernel(
    const float* __restrict__ Q, const float* __restrict__ K,
    const float* __restrict__ V, bf16* __restrict__ Ohi, bf16* __restrict__ Olo)
{
    __shared__ float Qs [64][64];
    __shared__ float KPs[64][64];
    __shared__ float Vs [64][64];

    const int tid = threadIdx.x;
    const int qt = blockIdx.x, hh = blockIdx.y, bb = blockIdx.z;
    const int ty = tid >> 4, tx = tid & 15;

    const size_t baseQ = ((size_t)(bb * TSEQ + qt * 64)) * CDIM + hh * DHEAD;

    #pragma unroll
    for (int it = 0; it < 4; it++) {
        const int idx = it * 256 + tid;
        const int r = idx >> 4;
        const int c = (idx & 15) << 2;
        float4 t = *(const float4*)&Q[baseQ + (size_t)r * CDIM + c];
        t.x *= 0.125f; t.y *= 0.125f; t.z *= 0.125f; t.w *= 0.125f;
        *(float4*)&Qs[r][c] = t;
    }

    float m[4], lsum[4], o[4][4];
    #pragma unroll
    for (int i = 0; i < 4; i++) {
        m[i] = -1e30f; lsum[i] = 0.f;
        #pragma unroll
        for (int j = 0; j < 4; j++) o[i][j] = 0.f;
    }

    for (int kt = 0; kt <= qt; kt++) {
        __syncthreads();
        const size_t baseK = ((size_t)(bb * TSEQ + kt * 64)) * CDIM + hh * DHEAD;
        #pragma unroll
        for (int it = 0; it < 4; it++) {
            const int idx = it * 256 + tid;
            const int r = idx >> 4;
            const int c = (idx & 15) << 2;
            const float4 tk = *(const float4*)&K[baseK + (size_t)r * CDIM + c];
            KPs[c + 0][r] = tk.x;
            KPs[c + 1][r] = tk.y;
            KPs[c + 2][r] = tk.z;
            KPs[c + 3][r] = tk.w;
            const float4 tv = *(const float4*)&V[baseK + (size_t)r * CDIM + c];
            *(float4*)&Vs[r][c] = tv;
        }
        __syncthreads();

        float s[4][4];
        #pragma unroll
        for (int i = 0; i < 4; i++)
            #pragma unroll
            for (int j = 0; j < 4; j++) s[i][j] = 0.f;

        #pragma unroll 16
        for (int d = 0; d < 64; d++) {
            float a[4], b[4];
            #pragma unroll
            for (int i = 0; i < 4; i++) a[i] = Qs[ty * 4 + i][d];
            #pragma unroll
            for (int j = 0; j < 4; j++) b[j] = KPs[d][tx * 4 + j];
            #pragma unroll
            for (int i = 0; i < 4; i++)
                #pragma unroll
                for (int j = 0; j < 4; j++)
                    s[i][j] = fmaf(a[i], b[j], s[i][j]);
        }

        if (kt == qt) {
            #pragma unroll
            for (int i = 0; i < 4; i++)
                #pragma unroll
                for (int j = 0; j < 4; j++)
                    if (tx * 4 + j > ty * 4 + i) s[i][j] = -1e30f;
        }

        float p[4][4];
        #pragma unroll
        for (int i = 0; i < 4; i++) {
            float mx = fmaxf(fmaxf(s[i][0], s[i][1]), fmaxf(s[i][2], s[i][3]));
            #pragma unroll
            for (int off = 1; off < 16; off <<= 1)
                mx = fmaxf(mx, __shfl_xor_sync(0xffffffffu, mx, off));
            const float mn = fmaxf(m[i], mx);
            const float alpha = __expf(m[i] - mn);
            m[i] = mn;
            float rs = 0.f;
            #pragma unroll
            for (int j = 0; j < 4; j++) {
                p[i][j] = __expf(s[i][j] - mn);
                rs += p[i][j];
            }
            #pragma unroll
            for (int off = 1; off < 16; off <<= 1)
                rs += __shfl_xor_sync(0xffffffffu, rs, off);
            lsum[i] = lsum[i] * alpha + rs;
            #pragma unroll
            for (int j = 0; j < 4; j++) o[i][j] *= alpha;
        }

        __syncthreads();
        #pragma unroll
        for (int i = 0; i < 4; i++)
            #pragma unroll
            for (int j = 0; j < 4; j++)
                KPs[ty * 4 + i][tx * 4 + j] = p[i][j];
        __syncthreads();

        #pragma unroll 16
        for (int kk = 0; kk < 64; kk++) {
            float a[4], b[4];
            #pragma unroll
            for (int i = 0; i < 4; i++) a[i] = KPs[ty * 4 + i][kk];
            #pragma unroll
            for (int j = 0; j < 4; j++) b[j] = Vs[kk][tx * 4 + j];
            #pragma unroll
            for (int i = 0; i < 4; i++)
                #pragma unroll
                for (int j = 0; j < 4; j++)
                    o[i][j] = fmaf(a[i], b[j], o[i][j]);
        }
    }

    #pragma unroll
    for (int i = 0; i < 4; i++) {
        const float invl = 1.0f / lsum[i];
        const float v0 = o[i][0] * invl, v1 = o[i][1] * invl;
        const float v2 = o[i][2] * invl, v3 = o[i][3] * invl;
        bf16 h0, h1, h2, h3, l0, l1, l2, l3;
        split1(v0, h0, l0); split1(v1, h1, l1);
        split1(v2, h2, l2); split1(v3, h3, l3);
        const bf162 ha = __halves2bfloat162(h0, h1);
        const bf162 hb = __halves2bfloat162(h2, h3);
        const bf162 la = __halves2bfloat162(l0, l1);
        const bf162 lb = __halves2bfloat162(l2, l3);
        uint2 uh, ul;
        uh.x = *(const uint32_t*)&ha; uh.y = *(const uint32_t*)&hb;
        ul.x = *(const uint32_t*)&la; ul.y = *(const uint32_t*)&lb;
        const size_t off = baseQ + (size_t)(ty * 4 + i) * CDIM + tx * 4;
        *(uint2*)&Ohi[off] = uh;
        *(uint2*)&Olo[off] = ul;
    }
}

// ==================== launch ===============================================
extern "C" void kernel_launch(void* const* d_in, const int* in_sizes, int n_in,
                              void* d_out, int out_size)
{
    (void)in_sizes; (void)n_in; (void)out_size;
    const float* x    = (const float*)d_in[0];
    const float* Wq   = (const float*)d_in[1];
    const float* Wk   = (const float*)d_in[2];
    const float* Wv   = (const float*)d_in[3];
    const float* Wo   = (const float*)d_in[4];
    const float* bo   = (const float*)d_in[5];
    const float* ln1g = (const float*)d_in[6];
    const float* ln1b = (const float*)d_in[7];
    const float* ln2g = (const float*)d_in[8];
    const float* ln2b = (const float*)d_in[9];
    const float* W1   = (const float*)d_in[10];
    const float* b1   = (const float*)d_in[11];
    const float* W2   = (const float*)d_in[12];
    const float* b2   = (const float*)d_in[13];
    float* out = (float*)d_out;

    bf16 *hhi, *hlo, *ahi, *alo, *ffhi, *fflo;
    float *q, *k, *v, *x1;
    bf16 *Wqhi, *Wqlo, *Wkhi, *Wklo, *Wvhi, *Wvlo, *Wohi, *Wolo;
    bf16 *W1hi, *W1lo, *W2hi, *W2lo;
    cudaGetSymbolAddress((void**)&hhi,  g_hhi);
    cudaGetSymbolAddress((void**)&hlo,  g_hlo);
    cudaGetSymbolAddress((void**)&q,    g_q);
    cudaGetSymbolAddress((void**)&k,    g_k);
    cudaGetSymbolAddress((void**)&v,    g_v);
    cudaGetSymbolAddress((void**)&ahi,  g_ahi);
    cudaGetSymbolAddress((void**)&alo,  g_alo);
    cudaGetSymbolAddress((void**)&x1,   g_x1);
    cudaGetSymbolAddress((void**)&ffhi, g_ffhi);
    cudaGetSymbolAddress((void**)&fflo, g_fflo);
    cudaGetSymbolAddress((void**)&Wqhi, g_Wqhi);
    cudaGetSymbolAddress((void**)&Wqlo, g_Wqlo);
    cudaGetSymbolAddress((void**)&Wkhi, g_Wkhi);
    cudaGetSymbolAddress((void**)&Wklo, g_Wklo);
    cudaGetSymbolAddress((void**)&Wvhi, g_Wvhi);
    cudaGetSymbolAddress((void**)&Wvlo, g_Wvlo);
    cudaGetSymbolAddress((void**)&Wohi, g_Wohi);
    cudaGetSymbolAddress((void**)&Wolo, g_Wolo);
    cudaGetSymbolAddress((void**)&W1hi, g_W1hi);
    cudaGetSymbolAddress((void**)&W1lo, g_W1lo);
    cudaGetSymbolAddress((void**)&W2hi, g_W2hi);
    cudaGetSymbolAddress((void**)&W2lo, g_W2lo);

    cudaFuncSetAttribute(mma_gemm_kernel<false, false, false, false>,
                         cudaFuncAttributeMaxDynamicSharedMemorySize, GEMM_SMEM);
    cudaFuncSetAttribute(mma_gemm_kernel<true, false, true, false>,
                         cudaFuncAttributeMaxDynamicSharedMemorySize, GEMM_SMEM);
    cudaFuncSetAttribute(mma_gemm_kernel<true, true, false, true>,
                         cudaFuncAttributeMaxDynamicSharedMemorySize, GEMM_SMEM);

    // 0) split weights to bf16 hi/lo
    wsplit_kernel<<<512, 256>>>(Wq, Wqhi, Wqlo, CDIM * CDIM / 4);
    wsplit_kernel<<<512, 256>>>(Wk, Wkhi, Wklo, CDIM * CDIM / 4);
    wsplit_kernel<<<512, 256>>>(Wv, Wvhi, Wvlo, CDIM * CDIM / 4);
    wsplit_kernel<<<512, 256>>>(Wo, Wohi, Wolo, CDIM * CDIM / 4);
    wsplit_kernel<<<1024, 256>>>(W1, W1hi, W1lo, CDIM * FDIM / 4);
    wsplit_kernel<<<1024, 256>>>(W2, W2hi, W2lo, FDIM * CDIM / 4);

    const dim3 gc(CDIM / 128, MTOT / 128);   // (8, 64)
    const dim3 gf(FDIM / 128, MTOT / 128);   // (32, 64)

    // 1) h = LN1(x), split
    layernorm_split_kernel<<<MTOT, 256>>>(x, ln1g, ln1b, hhi, hlo);
    // 2) q,k,v = h @ W{q,k,v}  (bf16x3 mma.sync, fp32 out)
    mma_gemm_kernel<false, false, false, false><<<gc, GT, GEMM_SMEM>>>(
        hhi, hlo, Wqhi, Wqlo, nullptr, nullptr, q, nullptr, nullptr, CDIM, CDIM);
    mma_gemm_kernel<false, false, false, false><<<gc, GT, GEMM_SMEM>>>(
        hhi, hlo, Wkhi, Wklo, nullptr, nullptr, k, nullptr, nullptr, CDIM, CDIM);
    mma_gemm_kernel<false, false, false, false><<<gc, GT, GEMM_SMEM>>>(
        hhi, hlo, Wvhi, Wvlo, nullptr, nullptr, v, nullptr, nullptr, CDIM, CDIM);
    // 3) causal attention (fp32 compute, split output)
    flash_attn_kernel<<<dim3(TSEQ / 64, HEADS, BB), 256>>>(q, k, v, ahi, alo);
    // 4) x1 = x + attn @ Wo + bo
    mma_gemm_kernel<true, false, true, false><<<gc, GT, GEMM_SMEM>>>(
        ahi, alo, Wohi, Wolo, bo, x, x1, nullptr, nullptr, CDIM, CDIM);
    // 5) h = LN2(x1), split
    layernorm_split_kernel<<<MTOT, 256>>>(x1, ln2g, ln2b, hhi, hlo);
    // 6) ff = relu(h @ W1 + b1), split output
    mma_gemm_kernel<true, true, false, true><<<gf, GT, GEMM_SMEM>>>(
        hhi, hlo, W1hi, W1lo, b1, nullptr, nullptr, ffhi, fflo, FDIM, CDIM);
    // 7) out = x1 + ff @ W2 + b2
    mma_gemm_kernel<true, false, true, false><<<gc, GT, GEMM_SMEM>>>(
        ffhi, fflo, W2hi, W2lo, b2, x1, out, nullptr, nullptr, CDIM, FDIM);
}